// round 16
// baseline (speedup 1.0000x reference)
#include <cuda_runtime.h>
#include <cstdint>

// Problem constants (fixed shapes)
#define BQ   4
#define KC   24
#define DD   16
#define NPIX (512 * 1024)
#define KP   17

// k_accum tiling
#define TILE        256
#define QROW        17
#define WREG        (32 * QROW)           // 544 floats per warp region
#define ACPY        392                   // 392 mod 32 = 8 -> halves' RMW banks disjoint
#define TILES_IMG   (NPIX / TILE)         // 2048 tiles per image
#define ABLK_X      185                   // 185*4 = 740 blocks = one wave @5/SM

// ---------------- device scratch (module-load zero; re-zeroed per replay) ----
__device__ float g_sums[BQ * KC * DD];
__device__ float g_counts[BQ * KC];
__device__ float g_centers[BQ * KC * DD];
__device__ float g_invc[BQ * KC];
__device__ float g_vtot;
__device__ float g_extra;
__device__ unsigned int g_done;

// ---------------- pass 1: warp-independent stage+gather, bank-clean RMW ------
__global__ void __launch_bounds__(256) k_accum(const float* __restrict__ data,
                                               const int*  __restrict__ labels) {
    __shared__ float s_data[8 * WREG];             // 17408 B, per-warp regions
    __shared__ float s_acc[16 * ACPY];             // 25088 B, stride-392 copies
    __shared__ int   s_h[8][KC + 4];               // 896 B

    const int t = threadIdx.x;
    const int w = t >> 5;
    const int lane = t & 31;
    const int half = lane >> 4;
    const int dlane = lane & 15;

    const int b = blockIdx.y;
    const float* dptr = data + (size_t)b * DD * NPIX;
    const int*   lptr = labels + (size_t)b * NPIX;

    for (int i = t; i < 16 * ACPY; i += 256) s_acc[i] = 0.f;
    for (int i = t; i < 8 * (KC + 4); i += 256) (&s_h[0][0])[i] = 0;
    __syncthreads();     // once, for s_acc/s_h init only

    float* wreg = &s_data[w * WREG];
    const int sd   = lane >> 3;            // base dim (0..3)
    const int spx  = lane & 7;             // pixel4 within warp's 8
    float* sbase = wreg + (4 * spx) * QROW + sd;

    const float* myrow0 = wreg + half * QROW + dlane;
    float* accb = &s_acc[(w * 2 + half) * ACPY + dlane];

    for (int tile = blockIdx.x; tile < TILES_IMG; tile += ABLK_X) {
        const int pv = tile * (TILE / 4) + w * 8 + spx;
        const int labReg = lptr[tile * TILE + w * 32 + lane];
        atomicAdd(&s_h[w][labReg], 1);

        // ---- self-stage own 32 points (conflict-free) ----
#pragma unroll
        for (int i = 0; i < 4; i++) {
            const int d = sd + 4 * i;
            const float4 v =
                reinterpret_cast<const float4*>(dptr + (size_t)d * NPIX)[pv];
            float* rp = sbase + 4 * i;
            rp[0 * QROW] = v.x;
            rp[1 * QROW] = v.y;
            rp[2 * QROW] = v.z;
            rp[3 * QROW] = v.w;
        }
        __syncwarp();

        // ---- gather: 2 points per iteration, conflict-free RMW (ACPY=392) --
#pragma unroll
        for (int i = 0; i < 16; i++) {
            const int myl = __shfl_sync(0xffffffffu, labReg, 2 * i + half);
            const float v = myrow0[i * (2 * QROW)];
            float* pa = accb + myl * DD;
            *pa += v;
        }
        __syncwarp();     // before next stage overwrites this warp's region
    }

    // ---- merge 16 sum-copies + 8 count-copies -> global ----
    __syncthreads();
    for (int o = t; o < KC * DD; o += 256) {
        float s = 0.f;
#pragma unroll
        for (int c = 0; c < 16; c++) s += s_acc[c * ACPY + o];
        atomicAdd(&g_sums[b * KC * DD + o], s);
    }
    if (t < KC) {
        int s = 0;
#pragma unroll
        for (int c = 0; c < 8; c++) s += s_h[c][t];
        atomicAdd(&g_counts[b * KC + t], (float)s);
    }
}

// ---------------- centers + dist + reg; re-zero state for next replay --------
__global__ void __launch_bounds__(256) k_centers() {
    __shared__ float s_c[BQ * KC * DD];
    __shared__ float s_ic[BQ * KC];
    __shared__ float s_red[8];
    const int t = threadIdx.x;

    if (t == 0) { g_vtot = 0.f; g_done = 0u; }

    if (t < BQ * KC) {
        const float cnt = g_counts[t];
        const float inv = 1.f / cnt;
        g_invc[t] = inv;
        s_ic[t] = inv;
    }
    __syncthreads();

    for (int i = t; i < BQ * KC * DD; i += 256) {
        const float c = g_sums[i] * s_ic[i >> 4];
        s_c[i] = c;
        g_centers[i] = c;
    }
    __syncthreads();

    const float inv_pairs = 1.f / (2.f * KC * (KC - 1));
    float acc = 0.f;
    for (int i = t; i < BQ * KC * KC; i += 256) {
        const int b = i / (KC * KC);
        const int r = i - b * KC * KC;
        const int k1 = r / KC, k2 = r - k1 * KC;
        const float* c1 = &s_c[(b * KC + k1) * DD];
        const float* c2 = &s_c[(b * KC + k2) * DD];
        float sq = 0.f;
#pragma unroll
        for (int d = 0; d < DD; d++) { const float df = c1[d] - c2[d]; sq += df * df; }
        const float cd = (k1 == k2) ? 0.f : sqrtf(sq);
        const float h  = fmaxf(2.f - cd, 0.f);
        acc += h * h * inv_pairs;
    }
    for (int i = t; i < BQ * KC; i += 256) {
        const float* c = &s_c[i * DD];
        float sq = 0.f;
#pragma unroll
        for (int d = 0; d < DD; d++) sq += c[d] * c[d];
        acc += sqrtf(sq) * (1.f / KC);
    }

#pragma unroll
    for (int o = 16; o > 0; o >>= 1)
        acc += __shfl_xor_sync(0xffffffffu, acc, o);
    if ((t & 31) == 0) s_red[t >> 5] = acc;
    __syncthreads();
    if (t < 8) {
        float v = s_red[t];
#pragma unroll
        for (int o = 4; o > 0; o >>= 1)
            v += __shfl_xor_sync(0xffu, v, o);
        if (t == 0) g_extra = v;
    }

    // re-zero accumulators for the next graph replay (consumed above)
    __syncthreads();
    for (int i = t; i < BQ * KC * DD; i += 256) g_sums[i] = 0.f;
    if (t < BQ * KC) g_counts[t] = 0.f;
}

// ---------------- pass 2: hinged variance + fused finalize (R8 verbatim) -----
__global__ void __launch_bounds__(256) k_var(const float* __restrict__ data,
                                             const int*  __restrict__ labels,
                                             float* __restrict__ out,
                                             int nblocks) {
    __shared__ float s_c[KC * KP];
    __shared__ float s_ic[KC];
    __shared__ float s_red[8];
    __shared__ bool s_last;
    const int t = threadIdx.x;
    const int b = blockIdx.y;

    for (int i = t; i < KC * DD; i += 256)
        s_c[(i >> 4) * KP + (i & 15)] = g_centers[b * KC * DD + i];
    if (t < KC) s_ic[t] = g_invc[b * KC + t];
    __syncthreads();

    const float* dptr = data + (size_t)b * DD * NPIX;
    const int*   lptr = labels + (size_t)b * NPIX;

    const int bx = gridDim.x - 1 - blockIdx.x;   // reversed: L2 reuse from pass 1
    const int vbase = bx * (256 * 2);

    float acc = 0.f;
#pragma unroll
    for (int it = 0; it < 2; it++) {
        const int vn = vbase + it * 256 + t;
        const int4 l4 = reinterpret_cast<const int4*>(lptr)[vn];
        const int o0 = l4.x * KP, o1 = l4.y * KP, o2 = l4.z * KP, o3 = l4.w * KP;
        float s0 = 0.f, s1 = 0.f, s2 = 0.f, s3 = 0.f;
#pragma unroll
        for (int d = 0; d < DD; d++) {
            const float4 v =
                reinterpret_cast<const float4*>(dptr + (size_t)d * NPIX)[vn];
            const float a0 = v.x - s_c[o0 + d]; s0 += a0 * a0;
            const float a1 = v.y - s_c[o1 + d]; s1 += a1 * a1;
            const float a2 = v.z - s_c[o2 + d]; s2 += a2 * a2;
            const float a3 = v.w - s_c[o3 + d]; s3 += a3 * a3;
        }
        const float h0 = fmaxf(sqrtf(s0) - 1.f, 0.f);
        const float h1 = fmaxf(sqrtf(s1) - 1.f, 0.f);
        const float h2 = fmaxf(sqrtf(s2) - 1.f, 0.f);
        const float h3 = fmaxf(sqrtf(s3) - 1.f, 0.f);
        acc += h0 * h0 * s_ic[l4.x];
        acc += h1 * h1 * s_ic[l4.y];
        acc += h2 * h2 * s_ic[l4.z];
        acc += h3 * h3 * s_ic[l4.w];
    }

#pragma unroll
    for (int o = 16; o > 0; o >>= 1)
        acc += __shfl_xor_sync(0xffffffffu, acc, o);
    if ((t & 31) == 0) s_red[t >> 5] = acc;
    __syncthreads();
    if (t < 8) {
        float v = s_red[t];
#pragma unroll
        for (int o = 4; o > 0; o >>= 1)
            v += __shfl_xor_sync(0xffu, v, o);
        if (t == 0) {
            atomicAdd(&g_vtot, v);
            __threadfence();
            const unsigned ticket = atomicAdd(&g_done, 1u);
            s_last = (ticket == (unsigned)(nblocks - 1));
        }
    }
    __syncthreads();
    if (s_last && t == 0) {
        const float vt = *(volatile float*)&g_vtot;
        out[0] = (vt + g_extra) * (1.f / BQ);
    }
}

// ---------------- entry point ----------------
extern "C" void kernel_launch(void* const* d_in, const int* in_sizes, int n_in,
                              void* d_out, int out_size) {
    const float* data   = (const float*)d_in[0];
    const int*   labels = (const int*)d_in[1];
    float* out = (float*)d_out;

    dim3 agrid(ABLK_X, BQ);
    k_accum<<<agrid, 256>>>(data, labels);

    k_centers<<<1, 256>>>();

    dim3 vgrid(NPIX / 2048, BQ);
    k_var<<<vgrid, 256>>>(data, labels, out, (NPIX / 2048) * BQ);
}

// round 17
// speedup vs baseline: 1.0620x; 1.0620x over previous
#include <cuda_runtime.h>
#include <cstdint>

// Problem constants (fixed shapes)
#define BQ   4
#define KC   24
#define DD   16
#define NPIX (512 * 1024)
#define KP   17

// k_accum tiling (R14 proven config)
#define TILE        256
#define QROW        17
#define WREG        (32 * QROW)           // 544 floats per warp region
#define TILES_IMG   (NPIX / TILE)         // 2048 tiles per image
#define ABLK_X      185                   // 185*4 = 740 blocks = one wave @5/SM

// ---------------- device scratch (module-load zero; re-zeroed per replay) ----
__device__ float g_sums[BQ * KC * DD];
__device__ float g_counts[BQ * KC];
__device__ float g_centers[BQ * KC * DD];
__device__ float g_invc[BQ * KC];
__device__ float g_vtot;
__device__ float g_extra;
__device__ unsigned int g_done;

// ---------------- pass 1: warp-independent stage+gather (R14, no syncwarps) --
__global__ void __launch_bounds__(256) k_accum(const float* __restrict__ data,
                                               const int*  __restrict__ labels) {
    __shared__ float s_data[8 * WREG];             // 17408 B, per-warp regions
    __shared__ float s_acc[8 * 2 * KC * DD];       // 24576 B
    __shared__ int   s_h[8][KC + 4];               // 896 B

    const int t = threadIdx.x;
    const int w = t >> 5;
    const int lane = t & 31;
    const int half = lane >> 4;
    const int dlane = lane & 15;

    const int b = blockIdx.y;
    const float* dptr = data + (size_t)b * DD * NPIX;
    const int*   lptr = labels + (size_t)b * NPIX;

    for (int i = t; i < 8 * 2 * KC * DD; i += 256) s_acc[i] = 0.f;
    for (int i = t; i < 8 * (KC + 4); i += 256) (&s_h[0][0])[i] = 0;
    __syncthreads();     // once, for s_acc/s_h init only

    float* wreg = &s_data[w * WREG];
    const int sd   = lane >> 3;            // base dim (0..3)
    const int spx  = lane & 7;             // pixel4 within warp's 8
    float* sbase = wreg + (4 * spx) * QROW + sd;

    const float* myrow0 = wreg + half * QROW + dlane;
    float* accb = &s_acc[((w * 2 + half) * KC) * DD + dlane];

    for (int tile = blockIdx.x; tile < TILES_IMG; tile += ABLK_X) {
        const int pv = tile * (TILE / 4) + w * 8 + spx;
        const int labReg = lptr[tile * TILE + w * 32 + lane];
        atomicAdd(&s_h[w][labReg], 1);

        // ---- self-stage own 32 points (conflict-free) ----
        // No syncwarp needed anywhere in this loop: the region is private to
        // this warp, and same-warp STS->LDS / LDS->STS ordering is guaranteed
        // by program order through the in-order LSU (may-alias blocks
        // compile-time reordering).
#pragma unroll
        for (int i = 0; i < 4; i++) {
            const int d = sd + 4 * i;
            const float4 v =
                reinterpret_cast<const float4*>(dptr + (size_t)d * NPIX)[pv];
            float* rp = sbase + 4 * i;
            rp[0 * QROW] = v.x;
            rp[1 * QROW] = v.y;
            rp[2 * QROW] = v.z;
            rp[3 * QROW] = v.w;
        }

        // ---- gather: 2 points per iteration, half-warp each ----
#pragma unroll
        for (int i = 0; i < 16; i++) {
            const int myl = __shfl_sync(0xffffffffu, labReg, 2 * i + half);
            const float v = myrow0[i * (2 * QROW)];
            float* pa = accb + myl * DD;
            *pa += v;
        }
    }

    // ---- merge 16 sum-copies + 8 count-copies -> global ----
    __syncthreads();
    for (int o = t; o < KC * DD; o += 256) {
        float s = 0.f;
#pragma unroll
        for (int c = 0; c < 16; c++) s += s_acc[c * (KC * DD) + o];
        atomicAdd(&g_sums[b * KC * DD + o], s);
    }
    if (t < KC) {
        int s = 0;
#pragma unroll
        for (int c = 0; c < 8; c++) s += s_h[c][t];
        atomicAdd(&g_counts[b * KC + t], (float)s);
    }
}

// ---------------- centers + dist + reg; re-zero state for next replay --------
__global__ void __launch_bounds__(256) k_centers() {
    __shared__ float s_c[BQ * KC * DD];
    __shared__ float s_ic[BQ * KC];
    __shared__ float s_red[8];
    const int t = threadIdx.x;

    if (t == 0) { g_vtot = 0.f; g_done = 0u; }

    if (t < BQ * KC) {
        const float cnt = g_counts[t];
        const float inv = 1.f / cnt;
        g_invc[t] = inv;
        s_ic[t] = inv;
    }
    __syncthreads();

    for (int i = t; i < BQ * KC * DD; i += 256) {
        const float c = g_sums[i] * s_ic[i >> 4];
        s_c[i] = c;
        g_centers[i] = c;
    }
    __syncthreads();

    const float inv_pairs = 1.f / (2.f * KC * (KC - 1));
    float acc = 0.f;
    for (int i = t; i < BQ * KC * KC; i += 256) {
        const int b = i / (KC * KC);
        const int r = i - b * KC * KC;
        const int k1 = r / KC, k2 = r - k1 * KC;
        const float* c1 = &s_c[(b * KC + k1) * DD];
        const float* c2 = &s_c[(b * KC + k2) * DD];
        float sq = 0.f;
#pragma unroll
        for (int d = 0; d < DD; d++) { const float df = c1[d] - c2[d]; sq += df * df; }
        const float cd = (k1 == k2) ? 0.f : sqrtf(sq);
        const float h  = fmaxf(2.f - cd, 0.f);
        acc += h * h * inv_pairs;
    }
    for (int i = t; i < BQ * KC; i += 256) {
        const float* c = &s_c[i * DD];
        float sq = 0.f;
#pragma unroll
        for (int d = 0; d < DD; d++) sq += c[d] * c[d];
        acc += sqrtf(sq) * (1.f / KC);
    }

#pragma unroll
    for (int o = 16; o > 0; o >>= 1)
        acc += __shfl_xor_sync(0xffffffffu, acc, o);
    if ((t & 31) == 0) s_red[t >> 5] = acc;
    __syncthreads();
    if (t < 8) {
        float v = s_red[t];
#pragma unroll
        for (int o = 4; o > 0; o >>= 1)
            v += __shfl_xor_sync(0xffu, v, o);
        if (t == 0) g_extra = v;
    }

    // re-zero accumulators for the next graph replay (consumed above)
    __syncthreads();
    for (int i = t; i < BQ * KC * DD; i += 256) g_sums[i] = 0.f;
    if (t < BQ * KC) g_counts[t] = 0.f;
}

// ---------------- pass 2: hinged variance + fused finalize (R8 verbatim) -----
__global__ void __launch_bounds__(256) k_var(const float* __restrict__ data,
                                             const int*  __restrict__ labels,
                                             float* __restrict__ out,
                                             int nblocks) {
    __shared__ float s_c[KC * KP];
    __shared__ float s_ic[KC];
    __shared__ float s_red[8];
    __shared__ bool s_last;
    const int t = threadIdx.x;
    const int b = blockIdx.y;

    for (int i = t; i < KC * DD; i += 256)
        s_c[(i >> 4) * KP + (i & 15)] = g_centers[b * KC * DD + i];
    if (t < KC) s_ic[t] = g_invc[b * KC + t];
    __syncthreads();

    const float* dptr = data + (size_t)b * DD * NPIX;
    const int*   lptr = labels + (size_t)b * NPIX;

    const int bx = gridDim.x - 1 - blockIdx.x;   // reversed: L2 reuse from pass 1
    const int vbase = bx * (256 * 2);

    float acc = 0.f;
#pragma unroll
    for (int it = 0; it < 2; it++) {
        const int vn = vbase + it * 256 + t;
        const int4 l4 = reinterpret_cast<const int4*>(lptr)[vn];
        const int o0 = l4.x * KP, o1 = l4.y * KP, o2 = l4.z * KP, o3 = l4.w * KP;
        float s0 = 0.f, s1 = 0.f, s2 = 0.f, s3 = 0.f;
#pragma unroll
        for (int d = 0; d < DD; d++) {
            const float4 v =
                reinterpret_cast<const float4*>(dptr + (size_t)d * NPIX)[vn];
            const float a0 = v.x - s_c[o0 + d]; s0 += a0 * a0;
            const float a1 = v.y - s_c[o1 + d]; s1 += a1 * a1;
            const float a2 = v.z - s_c[o2 + d]; s2 += a2 * a2;
            const float a3 = v.w - s_c[o3 + d]; s3 += a3 * a3;
        }
        const float h0 = fmaxf(sqrtf(s0) - 1.f, 0.f);
        const float h1 = fmaxf(sqrtf(s1) - 1.f, 0.f);
        const float h2 = fmaxf(sqrtf(s2) - 1.f, 0.f);
        const float h3 = fmaxf(sqrtf(s3) - 1.f, 0.f);
        acc += h0 * h0 * s_ic[l4.x];
        acc += h1 * h1 * s_ic[l4.y];
        acc += h2 * h2 * s_ic[l4.z];
        acc += h3 * h3 * s_ic[l4.w];
    }

#pragma unroll
    for (int o = 16; o > 0; o >>= 1)
        acc += __shfl_xor_sync(0xffffffffu, acc, o);
    if ((t & 31) == 0) s_red[t >> 5] = acc;
    __syncthreads();
    if (t < 8) {
        float v = s_red[t];
#pragma unroll
        for (int o = 4; o > 0; o >>= 1)
            v += __shfl_xor_sync(0xffu, v, o);
        if (t == 0) {
            atomicAdd(&g_vtot, v);
            __threadfence();
            const unsigned ticket = atomicAdd(&g_done, 1u);
            s_last = (ticket == (unsigned)(nblocks - 1));
        }
    }
    __syncthreads();
    if (s_last && t == 0) {
        const float vt = *(volatile float*)&g_vtot;
        out[0] = (vt + g_extra) * (1.f / BQ);
    }
}

// ---------------- entry point ----------------
extern "C" void kernel_launch(void* const* d_in, const int* in_sizes, int n_in,
                              void* d_out, int out_size) {
    const float* data   = (const float*)d_in[0];
    const int*   labels = (const int*)d_in[1];
    float* out = (float*)d_out;

    dim3 agrid(ABLK_X, BQ);
    k_accum<<<agrid, 256>>>(data, labels);

    k_centers<<<1, 256>>>();

    dim3 vgrid(NPIX / 2048, BQ);
    k_var<<<vgrid, 256>>>(data, labels, out, (NPIX / 2048) * BQ);
}